// round 4
// baseline (speedup 1.0000x reference)
#include <cuda_runtime.h>
#include <math.h>
#include <float.h>

#define B    64
#define H    224
#define W    224
#define HW   (H*W)
#define NTOT (B*HW)
#define NC   196
#define NBR  10
#define WINS 20
#define ITERS 50

#define ROWS  48      // 8 halo + 32 central + 8 halo
#define CROWS 32
#define CCOLS 16      // central cols per warp (lanes 8..23)
#define TPB   256

// ---------------- scratch (static device globals) ---------------------------
__device__ float         g_gray[NTOT];
__device__ float         g_wgm [NTOT];
__device__ float         g_wcd [4][NTOT];     // wgm + 10*cdiff[d]
__device__ float         g_dist[2][NTOT];
__device__ unsigned char g_mask[2][NTOT];
__device__ int           g_centi[B*NC*2];

// ---------------- phase 1: gray ----------------------------------------------
__global__ void k_gray(const float* __restrict__ x) {
    int i = blockIdx.x * blockDim.x + threadIdx.x;
    if (i >= NTOT) return;
    int b = i / HW;
    int r = i - b * HW;
    const float* xb = x + (size_t)b * 3 * HW;
    float R = xb[r], G = xb[HW + r], Bv = xb[2 * HW + r];
    float t = __fadd_rn(__fmul_rn(0.2989f, R), __fmul_rn(0.587f, G));
    g_gray[i] = __fadd_rn(t, __fmul_rn(0.114f, Bv));
}

// ---------------- phase 1: sobel -> grad + wgm -------------------------------
__device__ __forceinline__ float grayAt(const float* gb, int y, int x) {
    if ((unsigned)y >= (unsigned)H || (unsigned)x >= (unsigned)W) return 0.0f;
    return gb[y * W + x];
}

__global__ void k_grad(float* __restrict__ out_grad) {
    int i = blockIdx.x * blockDim.x + threadIdx.x;
    if (i >= NTOT) return;
    int b = i / HW;
    int r = i - b * HW;
    int y = r / W, x = r - y * W;
    const float* gb = g_gray + b * HW;

    float a00 = grayAt(gb, y - 1, x - 1), a01 = grayAt(gb, y - 1, x), a02 = grayAt(gb, y - 1, x + 1);
    float a10 = grayAt(gb, y,     x - 1),                             a12 = grayAt(gb, y,     x + 1);
    float a20 = grayAt(gb, y + 1, x - 1), a21 = grayAt(gb, y + 1, x), a22 = grayAt(gb, y + 1, x + 1);

    float gx = __fadd_rn(-a00, a02);
    gx = __fadd_rn(gx, __fmul_rn(-2.0f, a10));
    gx = __fadd_rn(gx, __fmul_rn( 2.0f, a12));
    gx = __fadd_rn(gx, -a20);
    gx = __fadd_rn(gx,  a22);
    float gy = __fadd_rn(-a00, __fmul_rn(-2.0f, a01));
    gy = __fadd_rn(gy, -a02);
    gy = __fadd_rn(gy,  a20);
    gy = __fadd_rn(gy, __fmul_rn(2.0f, a21));
    gy = __fadd_rn(gy,  a22);

    float s = __fadd_rn(__fadd_rn(__fmul_rn(gx, gx), __fmul_rn(gy, gy)), 1e-8f);
    float g = sqrtf(s);
    out_grad[i] = g;
    g_wgm[i] = __fmul_rn(powf(g, 4.0f), 10.0f);
}

// ---------------- phase 1: fused cost maps wcd[d] = wgm + 10*cdiff[d] --------
__global__ void k_wcd(const float* __restrict__ x) {
    int i = blockIdx.x * blockDim.x + threadIdx.x;
    if (i >= NTOT) return;
    int b = i / HW;
    int r = i - b * HW;
    int y = r / W, xx = r - y * W;
    const float* xb = x + (size_t)b * 3 * HW;

    float c0 = xb[r], c1 = xb[HW + r], c2 = xb[2 * HW + r];
    int yp = (y + 1 == H) ? 0 : y + 1;
    int ym = (y == 0) ? H - 1 : y - 1;
    int xp = (xx + 1 == W) ? 0 : xx + 1;
    int xm = (xx == 0) ? W - 1 : xx - 1;
    int nb[4];
    nb[0] = yp * W + xx;
    nb[1] = ym * W + xx;
    nb[2] = y  * W + xp;
    nb[3] = y  * W + xm;
    float w = g_wgm[i];
#pragma unroll
    for (int d = 0; d < 4; d++) {
        int n = nb[d];
        float s = __fadd_rn(__fadd_rn(fabsf(c0 - xb[n]), fabsf(c1 - xb[HW + n])),
                            fabsf(c2 - xb[2 * HW + n]));
        g_wcd[d][i] = __fadd_rn(w, __fmul_rn(s, 10.0f));
    }
}

// ---------------- phase 2: nearest-minima snap ------------------------------
#define OCCW ((HW + 31) / 32)

__device__ __forceinline__ float wredminf(float v) {
#pragma unroll
    for (int o = 16; o; o >>= 1) v = fminf(v, __shfl_xor_sync(0xffffffffu, v, o));
    return v;
}
__device__ __forceinline__ int wredmini(int v) {
#pragma unroll
    for (int o = 16; o; o >>= 1) v = min(v, __shfl_xor_sync(0xffffffffu, v, o));
    return v;
}

__global__ void k_cents(const float* __restrict__ grad, float* __restrict__ cents_out) {
    extern __shared__ unsigned char smraw[];
    float*        sg  = (float*)smraw;
    unsigned int* occ = (unsigned int*)(smraw + (size_t)HW * sizeof(float));
    __shared__ float smv[NC];
    __shared__ int   sli[NC];

    int b = blockIdx.x;
    int tid = threadIdx.x;
    const float* gb = grad + b * HW;
    for (int i = tid; i < HW; i += TPB) sg[i] = gb[i];
    for (int i = tid; i < OCCW; i += TPB) occ[i] = 0u;
    __syncthreads();

    int warp = tid >> 5, lane = tid & 31;
    for (int k = warp; k < NC; k += 8) {
        int cy = 8 + 16 * (k / 14);
        int cx = 8 + 16 * (k % 14);
        int ymin = max(0, cy - NBR), ymax = min(H, cy + NBR);
        int xmin = max(0, cx - NBR), xmax = min(W, cx + NBR);
        int h = ymax - ymin, w = xmax - xmin;

        float colmin = INFINITY;
        bool lv = (lane < w) && (lane < WINS);
        if (lv) {
            const float* col = sg + ymin * W + xmin + lane;
#pragma unroll
            for (int wy = 0; wy < WINS; wy++) {
                if (wy < h) colmin = fminf(colmin, col[wy * W]);
            }
        }
        float mv = wredminf(colmin);
        int li = WINS * WINS;
        if (lv) {
            const float* col = sg + ymin * W + xmin + lane;
#pragma unroll
            for (int wy = 0; wy < WINS; wy++) {
                if (wy < h && col[wy * W] == mv) { li = wy * WINS + lane; break; }
            }
        }
        li = wredmini(li);
        if (lane == 0) { smv[k] = mv; sli[k] = li; }
    }
    __syncthreads();

    if (tid == 0) {
        for (int k = 0; k < NC; k++) {
            int cy = 8 + 16 * (k / 14);
            int cx = 8 + 16 * (k % 14);
            int ymin = max(0, cy - NBR), ymax = min(H, cy + NBR);
            int xmin = max(0, cx - NBR), xmax = min(W, cx + NBR);
            int h = ymax - ymin, w = xmax - xmin;
            int ny = cy, nx = cx;
            bool found = false;
            int li = sli[k];
            float mv = smv[k];
            if (li < WINS * WINS) {
                int py = ymin + li / WINS, px = xmin + li % WINS;
                int bi = py * W + px;
                if (!((occ[bi >> 5] >> (bi & 31)) & 1u)) {
                    ny = py; nx = px; found = true;
                } else {
                    for (int l2 = 0; l2 < WINS * WINS; l2++) {
                        int wy = l2 / WINS, wx = l2 % WINS;
                        if (wy < h && wx < w) {
                            int b2 = (ymin + wy) * W + (xmin + wx);
                            if (sg[b2] == mv && !((occ[b2 >> 5] >> (b2 & 31)) & 1u)) {
                                ny = ymin + wy; nx = xmin + wx; found = true; break;
                            }
                        }
                    }
                }
            }
            if (found) {
                int bi = ny * W + nx;
                occ[bi >> 5] |= (1u << (bi & 31));
            }
            cents_out[(b * NC + k) * 2 + 0] = (float)ny;
            cents_out[(b * NC + k) * 2 + 1] = (float)nx;
            g_centi[(b * NC + k) * 2 + 0] = ny;
            g_centi[(b * NC + k) * 2 + 1] = nx;
        }
    }
}

// ---------------- phase 3: init + scatter ------------------------------------
__global__ void k_init() {
    int i = blockIdx.x * blockDim.x + threadIdx.x;
    if (i >= NTOT) return;
    g_dist[0][i] = INFINITY;
    g_mask[0][i] = 255;
}

__global__ void k_scatter() {
    int b = threadIdx.x;
    if (b >= B) return;
    for (int k = 0; k < NC; k++) {
        int ny = g_centi[(b * NC + k) * 2 + 0];
        int nx = g_centi[(b * NC + k) * 2 + 1];
        int idx = b * HW + ny * W + nx;
        g_dist[0][idx] = 0.0f;
        g_mask[0][idx] = (unsigned char)k;
    }
}

// ---------------- phase 3: warp-synchronous column propagation ---------------
// One warp per block; warp tile = 32 lanes (cols) x 48 rows, central 16x32.
// Vertical passes in registers, horizontal passes via shfl. ZERO barriers.
__global__ __launch_bounds__(32) void k_prop(int s, int niter, int last,
                                             float* __restrict__ out_mask) {
    __shared__ float sWc[4][ROWS][32];

    const int lane = threadIdx.x;
    const int ox = blockIdx.x * CCOLS;
    const int oy = blockIdx.y * CROWS;
    const int b  = blockIdx.z;

    const float*         dIn = g_dist[s];
    const unsigned char* mIn = g_mask[s];

    int gx = ox - 8 + lane;
    gx += (gx < 0) ? W : 0;
    gx -= (gx >= W) ? W : 0;

    float dd[ROWS];
    int   mm[ROWS];

#pragma unroll
    for (int r = 0; r < ROWS; r++) {
        int gy = oy - 8 + r;
        gy += (gy < 0) ? H : 0;
        gy -= (gy >= H) ? H : 0;
        int gi = b * HW + gy * W + gx;
        dd[r] = dIn[gi];
        mm[r] = mIn[gi];
        sWc[0][r][lane] = g_wcd[0][gi];
        sWc[1][r][lane] = g_wcd[1][gi];
        sWc[2][r][lane] = g_wcd[2][gi];
        sWc[3][r][lane] = g_wcd[3][gi];
    }
    __syncwarp();

#pragma unroll 1
    for (int it = 0; it < niter; it++) {
        // pass 0: dir (-1,0), read y+1 ; ascending rows (neighbor pre-pass)
#pragma unroll
        for (int r = 0; r < ROWS - 1; r++) {
            float wd = __fadd_rn(dd[r + 1], sWc[0][r][lane]);
            if (wd < dd[r]) { dd[r] = wd; mm[r] = mm[r + 1]; }
        }
        // pass 1: dir (1,0), read y-1 ; descending rows
#pragma unroll
        for (int r = ROWS - 1; r > 0; r--) {
            float wd = __fadd_rn(dd[r - 1], sWc[1][r][lane]);
            if (wd < dd[r]) { dd[r] = wd; mm[r] = mm[r - 1]; }
        }
        // pass 2: dir (0,-1), read x+1 ; shfl_down (pre-update via lockstep)
#pragma unroll
        for (int r = 0; r < ROWS; r++) {
            float nd = __shfl_down_sync(0xffffffffu, dd[r], 1);
            int   nm = __shfl_down_sync(0xffffffffu, mm[r], 1);
            float wd = __fadd_rn(nd, sWc[2][r][lane]);
            if (wd < dd[r]) { dd[r] = wd; mm[r] = nm; }
        }
        // pass 3: dir (0,1), read x-1 ; shfl_up
#pragma unroll
        for (int r = 0; r < ROWS; r++) {
            float nd = __shfl_up_sync(0xffffffffu, dd[r], 1);
            int   nm = __shfl_up_sync(0xffffffffu, mm[r], 1);
            float wd = __fadd_rn(nd, sWc[3][r][lane]);
            if (wd < dd[r]) { dd[r] = wd; mm[r] = nm; }
        }
    }

    // store central 16x32 (lanes 8..23, rows 8..39); no wrap needed
    if (lane >= 8 && lane < 8 + CCOLS) {
        int gbase = b * HW + oy * W + ox + (lane - 8);
        if (!last) {
            float*         dOut = g_dist[s ^ 1];
            unsigned char* mOut = g_mask[s ^ 1];
#pragma unroll
            for (int r = 8; r < 8 + CROWS; r++) {
                int gi = gbase + (r - 8) * W;
                dOut[gi] = dd[r];
                mOut[gi] = (unsigned char)mm[r];
            }
        } else {
#pragma unroll
            for (int r = 8; r < 8 + CROWS; r++) {
                int gi = gbase + (r - 8) * W;
                out_mask[gi] = (mm[r] == 255) ? -1.0f : (float)mm[r];
            }
        }
    }
}

// ---------------- launch ------------------------------------------------------
extern "C" void kernel_launch(void* const* d_in, const int* in_sizes, int n_in,
                              void* d_out, int out_size) {
    const float* x = (const float*)d_in[0];
    float* out = (float*)d_out;
    float* out_grad  = out;                       // (B,1,H,W)
    float* out_cents = out + NTOT;                // (B,196,2)
    float* out_mask  = out + NTOT + B * NC * 2;   // (B,H,W)

    const int T = 256;
    const int G = (NTOT + T - 1) / T;

    static const size_t centsSmem = (size_t)HW * sizeof(float) + (size_t)OCCW * sizeof(unsigned int);
    cudaFuncSetAttribute(k_cents, cudaFuncAttributeMaxDynamicSharedMemorySize, (int)centsSmem);

    k_gray <<<G, T>>>(x);
    k_grad <<<G, T>>>(out_grad);
    k_wcd  <<<G, T>>>(x);
    k_cents<<<B, TPB, centsSmem>>>(out_grad, out_cents);
    k_init <<<G, T>>>();
    k_scatter<<<1, 64>>>();

    dim3 pg(W / CCOLS, H / CROWS, B);   // 14 x 7 x 64 warps
    int s = 0;
    int remaining = ITERS;
    while (remaining > 0) {
        int it = remaining >= 8 ? 8 : remaining;
        remaining -= it;
        int last = (remaining == 0) ? 1 : 0;
        k_prop<<<pg, 32>>>(s, it, last, out_mask);
        s ^= 1;
    }
}

// round 5
// speedup vs baseline: 1.0093x; 1.0093x over previous
#include <cuda_runtime.h>
#include <math.h>
#include <float.h>

#define B    64
#define H    224
#define W    224
#define HW   (H*W)
#define NTOT (B*HW)
#define NC   196
#define NBR  10
#define WINS 20
#define ITERS 50

#define ROWS  48      // 8 halo + 32 central + 8 halo
#define CROWS 32
#define CCOLS 16      // central cols (lanes 8..23)
#define RPW   12      // rows per warp
#define TPB   256

// ---------------- scratch (static device globals) ---------------------------
__device__ float         g_gray[NTOT];
__device__ float         g_wcd [4][NTOT];     // wgm + 10*cdiff[d]
__device__ float         g_dist[2][NTOT];
__device__ unsigned char g_mask[2][NTOT];

// ---------------- phase 1: gray + dist/mask init -----------------------------
__global__ void k_gray(const float* __restrict__ x) {
    int i = blockIdx.x * blockDim.x + threadIdx.x;
    if (i >= NTOT) return;
    int b = i / HW;
    int r = i - b * HW;
    const float* xb = x + (size_t)b * 3 * HW;
    float R = xb[r], G = xb[HW + r], Bv = xb[2 * HW + r];
    float t = __fadd_rn(__fmul_rn(0.2989f, R), __fmul_rn(0.587f, G));
    g_gray[i] = __fadd_rn(t, __fmul_rn(0.114f, Bv));
    g_dist[0][i] = INFINITY;
    g_mask[0][i] = 255;
}

// ---------------- phase 1: sobel -> grad -> wgm -> wcd (fused) ---------------
__device__ __forceinline__ float grayAt(const float* gb, int y, int x) {
    if ((unsigned)y >= (unsigned)H || (unsigned)x >= (unsigned)W) return 0.0f;
    return gb[y * W + x];
}

__global__ void k_gradwcd(const float* __restrict__ x, float* __restrict__ out_grad) {
    int i = blockIdx.x * blockDim.x + threadIdx.x;
    if (i >= NTOT) return;
    int b = i / HW;
    int r = i - b * HW;
    int y = r / W, xx = r - y * W;
    const float* gb = g_gray + b * HW;

    float a00 = grayAt(gb, y - 1, xx - 1), a01 = grayAt(gb, y - 1, xx), a02 = grayAt(gb, y - 1, xx + 1);
    float a10 = grayAt(gb, y,     xx - 1),                              a12 = grayAt(gb, y,     xx + 1);
    float a20 = grayAt(gb, y + 1, xx - 1), a21 = grayAt(gb, y + 1, xx), a22 = grayAt(gb, y + 1, xx + 1);

    float gx = __fadd_rn(-a00, a02);
    gx = __fadd_rn(gx, __fmul_rn(-2.0f, a10));
    gx = __fadd_rn(gx, __fmul_rn( 2.0f, a12));
    gx = __fadd_rn(gx, -a20);
    gx = __fadd_rn(gx,  a22);
    float gy = __fadd_rn(-a00, __fmul_rn(-2.0f, a01));
    gy = __fadd_rn(gy, -a02);
    gy = __fadd_rn(gy,  a20);
    gy = __fadd_rn(gy, __fmul_rn(2.0f, a21));
    gy = __fadd_rn(gy,  a22);

    float s = __fadd_rn(__fadd_rn(__fmul_rn(gx, gx), __fmul_rn(gy, gy)), 1e-8f);
    float g = sqrtf(s);
    out_grad[i] = g;
    float wgm = __fmul_rn(powf(g, 4.0f), 10.0f);

    const float* xb = x + (size_t)b * 3 * HW;
    float c0 = xb[r], c1 = xb[HW + r], c2 = xb[2 * HW + r];
    int yp = (y + 1 == H) ? 0 : y + 1;
    int ym = (y == 0) ? H - 1 : y - 1;
    int xp = (xx + 1 == W) ? 0 : xx + 1;
    int xm = (xx == 0) ? W - 1 : xx - 1;
    int nb[4];
    nb[0] = yp * W + xx;
    nb[1] = ym * W + xx;
    nb[2] = y  * W + xp;
    nb[3] = y  * W + xm;
#pragma unroll
    for (int d = 0; d < 4; d++) {
        int n = nb[d];
        float sc = __fadd_rn(__fadd_rn(fabsf(c0 - xb[n]), fabsf(c1 - xb[HW + n])),
                             fabsf(c2 - xb[2 * HW + n]));
        g_wcd[d][i] = __fadd_rn(wgm, __fmul_rn(sc, 10.0f));
    }
}

// ---------------- phase 2: nearest-minima snap + seed scatter ----------------
#define OCCW ((HW + 31) / 32)

__device__ __forceinline__ float wredminf(float v) {
#pragma unroll
    for (int o = 16; o; o >>= 1) v = fminf(v, __shfl_xor_sync(0xffffffffu, v, o));
    return v;
}
__device__ __forceinline__ int wredmini(int v) {
#pragma unroll
    for (int o = 16; o; o >>= 1) v = min(v, __shfl_xor_sync(0xffffffffu, v, o));
    return v;
}

__global__ void k_cents(const float* __restrict__ grad, float* __restrict__ cents_out) {
    extern __shared__ unsigned char smraw[];
    float*        sg  = (float*)smraw;
    unsigned int* occ = (unsigned int*)(smraw + (size_t)HW * sizeof(float));
    __shared__ float smv[NC];
    __shared__ int   sli[NC];

    int b = blockIdx.x;
    int tid = threadIdx.x;
    const float* gb = grad + b * HW;
    for (int i = tid; i < HW; i += TPB) sg[i] = gb[i];
    for (int i = tid; i < OCCW; i += TPB) occ[i] = 0u;
    __syncthreads();

    int warp = tid >> 5, lane = tid & 31;
    for (int k = warp; k < NC; k += 8) {
        int cy = 8 + 16 * (k / 14);
        int cx = 8 + 16 * (k % 14);
        int ymin = max(0, cy - NBR), ymax = min(H, cy + NBR);
        int xmin = max(0, cx - NBR), xmax = min(W, cx + NBR);
        int h = ymax - ymin, w = xmax - xmin;

        float colmin = INFINITY;
        bool lv = (lane < w) && (lane < WINS);
        if (lv) {
            const float* col = sg + ymin * W + xmin + lane;
#pragma unroll
            for (int wy = 0; wy < WINS; wy++) {
                if (wy < h) colmin = fminf(colmin, col[wy * W]);
            }
        }
        float mv = wredminf(colmin);
        int li = WINS * WINS;
        if (lv) {
            const float* col = sg + ymin * W + xmin + lane;
#pragma unroll
            for (int wy = 0; wy < WINS; wy++) {
                if (wy < h && col[wy * W] == mv) { li = wy * WINS + lane; break; }
            }
        }
        li = wredmini(li);
        if (lane == 0) { smv[k] = mv; sli[k] = li; }
    }
    __syncthreads();

    if (tid == 0) {
        for (int k = 0; k < NC; k++) {
            int cy = 8 + 16 * (k / 14);
            int cx = 8 + 16 * (k % 14);
            int ymin = max(0, cy - NBR), ymax = min(H, cy + NBR);
            int xmin = max(0, cx - NBR), xmax = min(W, cx + NBR);
            int h = ymax - ymin, w = xmax - xmin;
            int ny = cy, nx = cx;
            bool found = false;
            int li = sli[k];
            float mv = smv[k];
            if (li < WINS * WINS) {
                int py = ymin + li / WINS, px = xmin + li % WINS;
                int bi = py * W + px;
                if (!((occ[bi >> 5] >> (bi & 31)) & 1u)) {
                    ny = py; nx = px; found = true;
                } else {
                    for (int l2 = 0; l2 < WINS * WINS; l2++) {
                        int wy = l2 / WINS, wx = l2 % WINS;
                        if (wy < h && wx < w) {
                            int b2 = (ymin + wy) * W + (xmin + wx);
                            if (sg[b2] == mv && !((occ[b2 >> 5] >> (b2 & 31)) & 1u)) {
                                ny = ymin + wy; nx = xmin + wx; found = true; break;
                            }
                        }
                    }
                }
            }
            if (found) {
                int bi = ny * W + nx;
                occ[bi >> 5] |= (1u << (bi & 31));
            }
            cents_out[(b * NC + k) * 2 + 0] = (float)ny;
            cents_out[(b * NC + k) * 2 + 1] = (float)nx;
            // fused seed scatter
            int gi = b * HW + ny * W + nx;
            g_dist[0][gi] = 0.0f;
            g_mask[0][gi] = (unsigned char)k;
        }
    }
}

// ---------------- phase 3: quad-warp column propagation ----------------------
// Block: 128 thr (4 warps). Tile: 32 lanes x 48 rows; warp wy owns 12 rows in
// registers. Vertical passes: registers + 1-row smem exchange (2 barriers/iter).
// Horizontal passes: shfl, barrier-free. Central output 16x32 (lanes 8..23,
// rows 8..39) valid after up to 8 iterations (erosion 1 ring/iter).
__global__ __launch_bounds__(128, 8) void k_prop(int s, int niter, int last,
                                                 float* __restrict__ out_mask) {
    __shared__ float sWc[4][ROWS][32];
    __shared__ float x0D[4][32]; __shared__ int x0M[4][32];
    __shared__ float x1D[4][32]; __shared__ int x1M[4][32];

    const int lane = threadIdx.x & 31;
    const int wy   = threadIdx.x >> 5;
    const int ox = blockIdx.x * CCOLS;
    const int oy = blockIdx.y * CROWS;
    const int b  = blockIdx.z;

    const float*         dIn = g_dist[s];
    const unsigned char* mIn = g_mask[s];

    int gx = ox - 8 + lane;
    gx += (gx < 0) ? W : 0;
    gx -= (gx >= W) ? W : 0;

    float dd[RPW];
    int   mm[RPW];

#pragma unroll
    for (int rr = 0; rr < RPW; rr++) {
        int R = wy * RPW + rr;
        int gy = oy - 8 + R;
        gy += (gy < 0) ? H : 0;
        gy -= (gy >= H) ? H : 0;
        int gi = b * HW + gy * W + gx;
        dd[rr] = dIn[gi];
        mm[rr] = mIn[gi];
        sWc[0][R][lane] = g_wcd[0][gi];
        sWc[1][R][lane] = g_wcd[1][gi];
        sWc[2][R][lane] = g_wcd[2][gi];
        sWc[3][R][lane] = g_wcd[3][gi];
    }
    __syncthreads();

#pragma unroll 1
    for (int it = 0; it < niter; it++) {
        // ---- pass 0: dir (-1,0), read y+1, ascending rows -------------------
        x0D[wy][lane] = dd[0];
        x0M[wy][lane] = mm[0];
        __syncthreads();
#pragma unroll
        for (int rr = 0; rr < RPW - 1; rr++) {
            float wd = __fadd_rn(dd[rr + 1], sWc[0][wy * RPW + rr][lane]);
            if (wd < dd[rr]) { dd[rr] = wd; mm[rr] = mm[rr + 1]; }
        }
        {
            float nd = (wy < 3) ? x0D[wy + 1][lane] : INFINITY;
            int   nm = (wy < 3) ? x0M[wy + 1][lane] : 0;
            float wd = __fadd_rn(nd, sWc[0][wy * RPW + RPW - 1][lane]);
            if (wd < dd[RPW - 1]) { dd[RPW - 1] = wd; mm[RPW - 1] = nm; }
        }
        // ---- pass 1: dir (1,0), read y-1, descending rows -------------------
        x1D[wy][lane] = dd[RPW - 1];
        x1M[wy][lane] = mm[RPW - 1];
        __syncthreads();
#pragma unroll
        for (int rr = RPW - 1; rr > 0; rr--) {
            float wd = __fadd_rn(dd[rr - 1], sWc[1][wy * RPW + rr][lane]);
            if (wd < dd[rr]) { dd[rr] = wd; mm[rr] = mm[rr - 1]; }
        }
        {
            float nd = (wy > 0) ? x1D[wy - 1][lane] : INFINITY;
            int   nm = (wy > 0) ? x1M[wy - 1][lane] : 0;
            float wd = __fadd_rn(nd, sWc[1][wy * RPW][lane]);
            if (wd < dd[0]) { dd[0] = wd; mm[0] = nm; }
        }
        // ---- pass 2: dir (0,-1), read x+1 via shfl_down ----------------------
#pragma unroll
        for (int rr = 0; rr < RPW; rr++) {
            float nd = __shfl_down_sync(0xffffffffu, dd[rr], 1);
            int   nm = __shfl_down_sync(0xffffffffu, mm[rr], 1);
            float wd = __fadd_rn(nd, sWc[2][wy * RPW + rr][lane]);
            if (wd < dd[rr]) { dd[rr] = wd; mm[rr] = nm; }
        }
        // ---- pass 3: dir (0,1), read x-1 via shfl_up -------------------------
#pragma unroll
        for (int rr = 0; rr < RPW; rr++) {
            float nd = __shfl_up_sync(0xffffffffu, dd[rr], 1);
            int   nm = __shfl_up_sync(0xffffffffu, mm[rr], 1);
            float wd = __fadd_rn(nd, sWc[3][wy * RPW + rr][lane]);
            if (wd < dd[rr]) { dd[rr] = wd; mm[rr] = nm; }
        }
    }

    // ---- store central 16x32 -------------------------------------------------
    if (lane >= 8 && lane < 8 + CCOLS) {
        if (!last) {
            float*         dOut = g_dist[s ^ 1];
            unsigned char* mOut = g_mask[s ^ 1];
#pragma unroll
            for (int rr = 0; rr < RPW; rr++) {
                int R = wy * RPW + rr;
                if (R >= 8 && R < 8 + CROWS) {
                    int gi = b * HW + (oy + R - 8) * W + ox + (lane - 8);
                    dOut[gi] = dd[rr];
                    mOut[gi] = (unsigned char)mm[rr];
                }
            }
        } else {
#pragma unroll
            for (int rr = 0; rr < RPW; rr++) {
                int R = wy * RPW + rr;
                if (R >= 8 && R < 8 + CROWS) {
                    int gi = b * HW + (oy + R - 8) * W + ox + (lane - 8);
                    out_mask[gi] = (mm[rr] == 255) ? -1.0f : (float)mm[rr];
                }
            }
        }
    }
}

// ---------------- launch ------------------------------------------------------
extern "C" void kernel_launch(void* const* d_in, const int* in_sizes, int n_in,
                              void* d_out, int out_size) {
    const float* x = (const float*)d_in[0];
    float* out = (float*)d_out;
    float* out_grad  = out;                       // (B,1,H,W)
    float* out_cents = out + NTOT;                // (B,196,2)
    float* out_mask  = out + NTOT + B * NC * 2;   // (B,H,W)

    const int T = 256;
    const int G = (NTOT + T - 1) / T;

    static const size_t centsSmem = (size_t)HW * sizeof(float) + (size_t)OCCW * sizeof(unsigned int);
    cudaFuncSetAttribute(k_cents, cudaFuncAttributeMaxDynamicSharedMemorySize, (int)centsSmem);

    k_gray   <<<G, T>>>(x);
    k_gradwcd<<<G, T>>>(x, out_grad);
    k_cents  <<<B, TPB, centsSmem>>>(out_grad, out_cents);

    dim3 pg(W / CCOLS, H / CROWS, B);   // 14 x 7 x 64 blocks of 128 thr
    int s = 0;
    int remaining = ITERS;
    while (remaining > 0) {
        int it = remaining >= 8 ? 8 : remaining;
        remaining -= it;
        int last = (remaining == 0) ? 1 : 0;
        k_prop<<<pg, 128>>>(s, it, last, out_mask);
        s ^= 1;
    }
}

// round 6
// speedup vs baseline: 1.1933x; 1.1823x over previous
#include <cuda_runtime.h>
#include <math.h>
#include <float.h>

#define B    64
#define H    224
#define W    224
#define HW   (H*W)
#define NTOT (B*HW)
#define NC   196
#define NBR  10
#define WINS 20
#define ITERS 50

// propagation tile geometry
#define HALO  8
#define CC    48            // central cols
#define CR    32            // central rows
#define RC    64            // region cols  = CC + 2*HALO
#define RR    48            // region rows  = CR + 2*HALO
#define PWARPS 8
#define RPW   6             // rows per warp
#define TPB   256

// ---------------- scratch (static device globals) ---------------------------
__device__ float         g_wcd [4][NTOT];     // wgm + 10*cdiff[d]
__device__ float         g_dist[2][NTOT];
__device__ unsigned char g_mask[2][NTOT];

// ---------------- phase 1: fused gray/sobel/wgm/wcd + init (smem-tiled) ------
// block 256 thr -> 32x8 output tile, smem holds 34x10 halo tile of 3 channels.
#define GT_W 34
#define GT_H 10

__global__ __launch_bounds__(256) void k_gradwcd(const float* __restrict__ x,
                                                 float* __restrict__ out_grad) {
    __shared__ float sc0[GT_H][GT_W];
    __shared__ float sc1[GT_H][GT_W];
    __shared__ float sc2[GT_H][GT_W];
    __shared__ float sgr[GT_H][GT_W];

    const int tid = threadIdx.x;
    const int ox = blockIdx.x * 32;
    const int oy = blockIdx.y * 8;
    const int b  = blockIdx.z;
    const float* xb = x + (size_t)b * 3 * HW;

    for (int idx = tid; idx < GT_W * GT_H; idx += 256) {
        int ly = idx / GT_W, lx = idx - ly * GT_W;
        int gy = oy - 1 + ly; gy += (gy < 0) ? H : 0; gy -= (gy >= H) ? H : 0;
        int gx = ox - 1 + lx; gx += (gx < 0) ? W : 0; gx -= (gx >= W) ? W : 0;
        int gi = gy * W + gx;
        float R = xb[gi], G = xb[HW + gi], Bv = xb[2 * HW + gi];
        sc0[ly][lx] = R; sc1[ly][lx] = G; sc2[ly][lx] = Bv;
        float t = __fadd_rn(__fmul_rn(0.2989f, R), __fmul_rn(0.587f, G));
        sgr[ly][lx] = __fadd_rn(t, __fmul_rn(0.114f, Bv));
    }
    __syncthreads();

    const int tx = tid & 31, ty = tid >> 5;
    const int y = oy + ty, xx = ox + tx;
    const int ly = ty + 1, lx = tx + 1;

    // sobel with zero-padding (only use smem value when global tap in-bounds)
    #define TAP(dy, dx) ((((unsigned)(y + (dy)) < (unsigned)H) && ((unsigned)(xx + (dx)) < (unsigned)W)) ? sgr[ly + (dy)][lx + (dx)] : 0.0f)
    float a00 = TAP(-1,-1), a01 = TAP(-1,0), a02 = TAP(-1,1);
    float a10 = TAP(0,-1),                   a12 = TAP(0,1);
    float a20 = TAP(1,-1),  a21 = TAP(1,0),  a22 = TAP(1,1);
    #undef TAP

    float gx2 = __fadd_rn(-a00, a02);
    gx2 = __fadd_rn(gx2, __fmul_rn(-2.0f, a10));
    gx2 = __fadd_rn(gx2, __fmul_rn( 2.0f, a12));
    gx2 = __fadd_rn(gx2, -a20);
    gx2 = __fadd_rn(gx2,  a22);
    float gy2 = __fadd_rn(-a00, __fmul_rn(-2.0f, a01));
    gy2 = __fadd_rn(gy2, -a02);
    gy2 = __fadd_rn(gy2,  a20);
    gy2 = __fadd_rn(gy2, __fmul_rn(2.0f, a21));
    gy2 = __fadd_rn(gy2,  a22);

    float s = __fadd_rn(__fadd_rn(__fmul_rn(gx2, gx2), __fmul_rn(gy2, gy2)), 1e-8f);
    float g = sqrtf(s);
    int gi = b * HW + y * W + xx;
    out_grad[gi] = g;
    float wgm = __fmul_rn(powf(g, 4.0f), 10.0f);

    float c0 = sc0[ly][lx], c1 = sc1[ly][lx], c2 = sc2[ly][lx];
    // dirs: 0:(−1,0) nb y+1 | 1:(1,0) nb y−1 | 2:(0,−1) nb x+1 | 3:(0,1) nb x−1
    const int ndy[4] = {1, -1, 0, 0};
    const int ndx[4] = {0, 0, 1, -1};
#pragma unroll
    for (int d = 0; d < 4; d++) {
        int ny = ly + ndy[d], nx = lx + ndx[d];
        float sc = __fadd_rn(__fadd_rn(fabsf(c0 - sc0[ny][nx]), fabsf(c1 - sc1[ny][nx])),
                             fabsf(c2 - sc2[ny][nx]));
        g_wcd[d][gi] = __fadd_rn(wgm, __fmul_rn(sc, 10.0f));
    }
    g_dist[0][gi] = INFINITY;
    g_mask[0][gi] = 255;
}

// ---------------- phase 2: nearest-minima snap + seed scatter ----------------
#define OCCW ((HW + 31) / 32)

__device__ __forceinline__ float wredminf(float v) {
#pragma unroll
    for (int o = 16; o; o >>= 1) v = fminf(v, __shfl_xor_sync(0xffffffffu, v, o));
    return v;
}
__device__ __forceinline__ int wredmini(int v) {
#pragma unroll
    for (int o = 16; o; o >>= 1) v = min(v, __shfl_xor_sync(0xffffffffu, v, o));
    return v;
}

__global__ void k_cents(const float* __restrict__ grad, float* __restrict__ cents_out) {
    extern __shared__ unsigned char smraw[];
    float*        sg  = (float*)smraw;
    unsigned int* occ = (unsigned int*)(smraw + (size_t)HW * sizeof(float));
    __shared__ float smv[NC];
    __shared__ int   sli[NC];

    int b = blockIdx.x;
    int tid = threadIdx.x;
    const float* gb = grad + b * HW;
    for (int i = tid; i < HW; i += TPB) sg[i] = gb[i];
    for (int i = tid; i < OCCW; i += TPB) occ[i] = 0u;
    __syncthreads();

    int warp = tid >> 5, lane = tid & 31;
    for (int k = warp; k < NC; k += 8) {
        int cy = 8 + 16 * (k / 14);
        int cx = 8 + 16 * (k % 14);
        int ymin = max(0, cy - NBR), ymax = min(H, cy + NBR);
        int xmin = max(0, cx - NBR), xmax = min(W, cx + NBR);
        int h = ymax - ymin, w = xmax - xmin;

        float colmin = INFINITY;
        bool lv = (lane < w) && (lane < WINS);
        if (lv) {
            const float* col = sg + ymin * W + xmin + lane;
#pragma unroll
            for (int wy = 0; wy < WINS; wy++) {
                if (wy < h) colmin = fminf(colmin, col[wy * W]);
            }
        }
        float mv = wredminf(colmin);
        int li = WINS * WINS;
        if (lv) {
            const float* col = sg + ymin * W + xmin + lane;
#pragma unroll
            for (int wy = 0; wy < WINS; wy++) {
                if (wy < h && col[wy * W] == mv) { li = wy * WINS + lane; break; }
            }
        }
        li = wredmini(li);
        if (lane == 0) { smv[k] = mv; sli[k] = li; }
    }
    __syncthreads();

    if (tid == 0) {
        for (int k = 0; k < NC; k++) {
            int cy = 8 + 16 * (k / 14);
            int cx = 8 + 16 * (k % 14);
            int ymin = max(0, cy - NBR), ymax = min(H, cy + NBR);
            int xmin = max(0, cx - NBR), xmax = min(W, cx + NBR);
            int h = ymax - ymin, w = xmax - xmin;
            int ny = cy, nx = cx;
            bool found = false;
            int li = sli[k];
            float mv = smv[k];
            if (li < WINS * WINS) {
                int py = ymin + li / WINS, px = xmin + li % WINS;
                int bi = py * W + px;
                if (!((occ[bi >> 5] >> (bi & 31)) & 1u)) {
                    ny = py; nx = px; found = true;
                } else {
                    for (int l2 = 0; l2 < WINS * WINS; l2++) {
                        int wy = l2 / WINS, wx = l2 % WINS;
                        if (wy < h && wx < w) {
                            int b2 = (ymin + wy) * W + (xmin + wx);
                            if (sg[b2] == mv && !((occ[b2 >> 5] >> (b2 & 31)) & 1u)) {
                                ny = ymin + wy; nx = xmin + wx; found = true; break;
                            }
                        }
                    }
                }
            }
            if (found) {
                int bi = ny * W + nx;
                occ[bi >> 5] |= (1u << (bi & 31));
            }
            cents_out[(b * NC + k) * 2 + 0] = (float)ny;
            cents_out[(b * NC + k) * 2 + 1] = (float)nx;
            int gi = b * HW + ny * W + nx;
            g_dist[0][gi] = 0.0f;
            g_mask[0][gi] = (unsigned char)k;
        }
    }
}

// ---------------- phase 3: 2-col/thread multi-warp propagation ---------------
// Block 256 thr (8 warps). Region 64x48; warp w owns rows w*6..w*6+5, thread
// owns column pair (2L, 2L+1). Vertical passes: registers + boundary-row smem
// exchange (2 barriers/iter). Horizontal passes: 1 shfl-pair per 2 px.
#define SM_WC   0                       // float2 [4][RR][32] = 49152
#define SM_XAD  49152                   // float2 [8][32]     = 2048
#define SM_XBD  (49152 + 2048)          // float2 [8][32]     = 2048
#define SM_XAM  (49152 + 4096)          // uchar2 [8][32]     = 512
#define SM_XBM  (49152 + 4608)          // uchar2 [8][32]     = 512
#define PROP_SMEM (49152 + 5120)

__global__ __launch_bounds__(256, 4) void k_prop(int s, int niter, int last,
                                                 float* __restrict__ out_mask) {
    extern __shared__ unsigned char psm[];
    float2 (*sWc)[RR][32] = (float2(*)[RR][32])(psm + SM_WC);
    float2* xAD = (float2*)(psm + SM_XAD);
    float2* xBD = (float2*)(psm + SM_XBD);
    uchar2* xAM = (uchar2*)(psm + SM_XAM);
    uchar2* xBM = (uchar2*)(psm + SM_XBM);

    const int tid  = threadIdx.x;
    const int lane = tid & 31;
    const int w    = tid >> 5;
    const int ox = blockIdx.x * CC;
    const int oy = blockIdx.y * CR;
    const int b  = blockIdx.z;

    const float*         dIn = g_dist[s];
    const unsigned char* mIn = g_mask[s];

    // ---- load wcd into smem as float2 (coalesced) ---------------------------
    for (int idx = tid; idx < 4 * RR * 32; idx += 256) {
        int d  = idx / (RR * 32);
        int rm = idx - d * (RR * 32);
        int R  = rm >> 5;
        int L  = rm & 31;
        int gy = oy - HALO + R; gy += (gy < 0) ? H : 0; gy -= (gy >= H) ? H : 0;
        int gx = ox - HALO + 2 * L; gx += (gx < 0) ? W : 0; gx -= (gx >= W) ? W : 0;
        int gi = b * HW + gy * W + gx;
        sWc[d][R][L] = *(const float2*)(&g_wcd[d][gi]);
    }

    // ---- load own dist/mask columns -----------------------------------------
    int gx0 = ox - HALO + 2 * lane; gx0 += (gx0 < 0) ? W : 0; gx0 -= (gx0 >= W) ? W : 0;
    float d0[RPW], d1[RPW];
    int   m0[RPW], m1[RPW];
    int   gidx[RPW];
#pragma unroll
    for (int r = 0; r < RPW; r++) {
        int R = w * RPW + r;
        int gy = oy - HALO + R; gy += (gy < 0) ? H : 0; gy -= (gy >= H) ? H : 0;
        int gi = b * HW + gy * W + gx0;
        gidx[r] = gi;
        float2 dv = *(const float2*)(dIn + gi);
        uchar2 mv = *(const uchar2*)(mIn + gi);
        d0[r] = dv.x; d1[r] = dv.y;
        m0[r] = mv.x; m1[r] = mv.y;
    }
    __syncthreads();

#pragma unroll 1
    for (int it = 0; it < niter; it++) {
        // ---- pass 0: dir (-1,0), read y+1, rows ascending --------------------
        xAD[w * 32 + lane] = make_float2(d0[0], d1[0]);
        xAM[w * 32 + lane] = make_uchar2((unsigned char)m0[0], (unsigned char)m1[0]);
        __syncthreads();
#pragma unroll
        for (int r = 0; r < RPW - 1; r++) {
            float2 wc = sWc[0][w * RPW + r][lane];
            float f0 = __fadd_rn(d0[r + 1], wc.x); if (f0 < d0[r]) { d0[r] = f0; m0[r] = m0[r + 1]; }
            float f1 = __fadd_rn(d1[r + 1], wc.y); if (f1 < d1[r]) { d1[r] = f1; m1[r] = m1[r + 1]; }
        }
        {
            float2 nd = (w < PWARPS - 1) ? xAD[(w + 1) * 32 + lane] : make_float2(INFINITY, INFINITY);
            uchar2 nm = (w < PWARPS - 1) ? xAM[(w + 1) * 32 + lane] : make_uchar2(0, 0);
            float2 wc = sWc[0][w * RPW + RPW - 1][lane];
            float f0 = __fadd_rn(nd.x, wc.x); if (f0 < d0[RPW - 1]) { d0[RPW - 1] = f0; m0[RPW - 1] = nm.x; }
            float f1 = __fadd_rn(nd.y, wc.y); if (f1 < d1[RPW - 1]) { d1[RPW - 1] = f1; m1[RPW - 1] = nm.y; }
        }
        // ---- pass 1: dir (1,0), read y-1, rows descending ---------------------
        xBD[w * 32 + lane] = make_float2(d0[RPW - 1], d1[RPW - 1]);
        xBM[w * 32 + lane] = make_uchar2((unsigned char)m0[RPW - 1], (unsigned char)m1[RPW - 1]);
        __syncthreads();
#pragma unroll
        for (int r = RPW - 1; r > 0; r--) {
            float2 wc = sWc[1][w * RPW + r][lane];
            float f0 = __fadd_rn(d0[r - 1], wc.x); if (f0 < d0[r]) { d0[r] = f0; m0[r] = m0[r - 1]; }
            float f1 = __fadd_rn(d1[r - 1], wc.y); if (f1 < d1[r]) { d1[r] = f1; m1[r] = m1[r - 1]; }
        }
        {
            float2 nd = (w > 0) ? xBD[(w - 1) * 32 + lane] : make_float2(INFINITY, INFINITY);
            uchar2 nm = (w > 0) ? xBM[(w - 1) * 32 + lane] : make_uchar2(0, 0);
            float2 wc = sWc[1][w * RPW][lane];
            float f0 = __fadd_rn(nd.x, wc.x); if (f0 < d0[0]) { d0[0] = f0; m0[0] = nm.x; }
            float f1 = __fadd_rn(nd.y, wc.y); if (f1 < d1[0]) { d1[0] = f1; m1[0] = nm.y; }
        }
        // ---- pass 2: dir (0,-1), read x+1 -------------------------------------
#pragma unroll
        for (int r = 0; r < RPW; r++) {
            float o0 = d0[r], o1 = d1[r];
            int   q0 = m0[r], q1 = m1[r];
            float sh = __shfl_down_sync(0xffffffffu, o0, 1);
            int   sm = __shfl_down_sync(0xffffffffu, q0, 1);
            float2 wc = sWc[2][w * RPW + r][lane];
            float f0 = __fadd_rn(o1, wc.x); if (f0 < o0) { d0[r] = f0; m0[r] = q1; }
            float f1 = __fadd_rn(sh, wc.y); if (f1 < o1) { d1[r] = f1; m1[r] = sm; }
        }
        // ---- pass 3: dir (0,1), read x-1 --------------------------------------
#pragma unroll
        for (int r = 0; r < RPW; r++) {
            float o0 = d0[r], o1 = d1[r];
            int   q0 = m0[r], q1 = m1[r];
            float sh = __shfl_up_sync(0xffffffffu, o1, 1);
            int   sm = __shfl_up_sync(0xffffffffu, q1, 1);
            float2 wc = sWc[3][w * RPW + r][lane];
            float f1 = __fadd_rn(o0, wc.y); if (f1 < o1) { d1[r] = f1; m1[r] = q0; }
            float f0 = __fadd_rn(sh, wc.x); if (f0 < o0) { d0[r] = f0; m0[r] = sm; }
        }
    }

    // ---- store central CC x CR ------------------------------------------------
    // central local cols [8,56) -> lanes [4,28); central local rows [8,40)
    if (lane >= 4 && lane < 28) {
        int gx = ox - HALO + 2 * lane;              // un-wrapped; central => >= 0
        if (gx < W) {                               // guard right-edge padding tile
            if (!last) {
                float*         dOut = g_dist[s ^ 1];
                unsigned char* mOut = g_mask[s ^ 1];
#pragma unroll
                for (int r = 0; r < RPW; r++) {
                    int R = w * RPW + r;
                    if (R >= HALO && R < HALO + CR) {
                        int gi = gidx[r];
                        *(float2*)(dOut + gi) = make_float2(d0[r], d1[r]);
                        *(uchar2*)(mOut + gi) = make_uchar2((unsigned char)m0[r], (unsigned char)m1[r]);
                    }
                }
            } else {
#pragma unroll
                for (int r = 0; r < RPW; r++) {
                    int R = w * RPW + r;
                    if (R >= HALO && R < HALO + CR) {
                        int gi = gidx[r];
                        float v0 = (m0[r] == 255) ? -1.0f : (float)m0[r];
                        float v1 = (m1[r] == 255) ? -1.0f : (float)m1[r];
                        *(float2*)(out_mask + gi) = make_float2(v0, v1);
                    }
                }
            }
        }
    }
}

// ---------------- launch ------------------------------------------------------
extern "C" void kernel_launch(void* const* d_in, const int* in_sizes, int n_in,
                              void* d_out, int out_size) {
    const float* x = (const float*)d_in[0];
    float* out = (float*)d_out;
    float* out_grad  = out;                       // (B,1,H,W)
    float* out_cents = out + NTOT;                // (B,196,2)
    float* out_mask  = out + NTOT + B * NC * 2;   // (B,H,W)

    static const size_t centsSmem = (size_t)HW * sizeof(float) + (size_t)OCCW * sizeof(unsigned int);
    cudaFuncSetAttribute(k_cents, cudaFuncAttributeMaxDynamicSharedMemorySize, (int)centsSmem);
    cudaFuncSetAttribute(k_prop, cudaFuncAttributeMaxDynamicSharedMemorySize, PROP_SMEM);

    dim3 gg(W / 32, H / 8, B);                    // 7 x 28 x 64
    k_gradwcd<<<gg, 256>>>(x, out_grad);
    k_cents  <<<B, TPB, centsSmem>>>(out_grad, out_cents);

    dim3 pg((W + CC - 1) / CC, H / CR, B);        // 5 x 7 x 64
    int s = 0;
    int remaining = ITERS;
    while (remaining > 0) {
        int it = remaining >= HALO ? HALO : remaining;
        remaining -= it;
        int last = (remaining == 0) ? 1 : 0;
        k_prop<<<pg, 256, PROP_SMEM>>>(s, it, last, out_mask);
        s ^= 1;
    }
}

// round 7
// speedup vs baseline: 1.1964x; 1.0026x over previous
#include <cuda_runtime.h>
#include <math.h>
#include <float.h>

#define B    64
#define H    224
#define W    224
#define HW   (H*W)
#define NTOT (B*HW)
#define NC   196
#define NBR  10
#define WINS 20
#define ITERS 50

// propagation tile geometry
#define HALO  8
#define CC    48            // central cols
#define CR    32            // central rows
#define RC    64            // region cols  = CC + 2*HALO
#define RR    48            // region rows  = CR + 2*HALO
#define PWARPS 8
#define RPW   6             // rows per warp
#define TPB   256

// ---------------- scratch (static device globals) ---------------------------
__device__ float         g_wcd [4][NTOT];     // wgm + 10*cdiff[d]
__device__ float         g_dist[2][NTOT];
__device__ unsigned char g_mask[2][NTOT];

// ---------------- phase 1: fused gray/sobel/wgm/wcd + init (smem-tiled) ------
// block 256 thr -> 32x8 output tile, smem holds 34x10 halo tile of 3 channels.
#define GT_W 34
#define GT_H 10

__global__ __launch_bounds__(256) void k_gradwcd(const float* __restrict__ x,
                                                 float* __restrict__ out_grad) {
    __shared__ float sc0[GT_H][GT_W];
    __shared__ float sc1[GT_H][GT_W];
    __shared__ float sc2[GT_H][GT_W];
    __shared__ float sgr[GT_H][GT_W];

    const int tid = threadIdx.x;
    const int ox = blockIdx.x * 32;
    const int oy = blockIdx.y * 8;
    const int b  = blockIdx.z;
    const float* xb = x + (size_t)b * 3 * HW;

    for (int idx = tid; idx < GT_W * GT_H; idx += 256) {
        int ly = idx / GT_W, lx = idx - ly * GT_W;
        int gy = oy - 1 + ly; gy += (gy < 0) ? H : 0; gy -= (gy >= H) ? H : 0;
        int gx = ox - 1 + lx; gx += (gx < 0) ? W : 0; gx -= (gx >= W) ? W : 0;
        int gi = gy * W + gx;
        float R = xb[gi], G = xb[HW + gi], Bv = xb[2 * HW + gi];
        sc0[ly][lx] = R; sc1[ly][lx] = G; sc2[ly][lx] = Bv;
        float t = __fadd_rn(__fmul_rn(0.2989f, R), __fmul_rn(0.587f, G));
        sgr[ly][lx] = __fadd_rn(t, __fmul_rn(0.114f, Bv));
    }
    __syncthreads();

    const int tx = tid & 31, ty = tid >> 5;
    const int y = oy + ty, xx = ox + tx;
    const int ly = ty + 1, lx = tx + 1;

    // sobel with zero-padding (only use smem value when global tap in-bounds)
    #define TAP(dy, dx) ((((unsigned)(y + (dy)) < (unsigned)H) && ((unsigned)(xx + (dx)) < (unsigned)W)) ? sgr[ly + (dy)][lx + (dx)] : 0.0f)
    float a00 = TAP(-1,-1), a01 = TAP(-1,0), a02 = TAP(-1,1);
    float a10 = TAP(0,-1),                   a12 = TAP(0,1);
    float a20 = TAP(1,-1),  a21 = TAP(1,0),  a22 = TAP(1,1);
    #undef TAP

    float gx2 = __fadd_rn(-a00, a02);
    gx2 = __fadd_rn(gx2, __fmul_rn(-2.0f, a10));
    gx2 = __fadd_rn(gx2, __fmul_rn( 2.0f, a12));
    gx2 = __fadd_rn(gx2, -a20);
    gx2 = __fadd_rn(gx2,  a22);
    float gy2 = __fadd_rn(-a00, __fmul_rn(-2.0f, a01));
    gy2 = __fadd_rn(gy2, -a02);
    gy2 = __fadd_rn(gy2,  a20);
    gy2 = __fadd_rn(gy2, __fmul_rn(2.0f, a21));
    gy2 = __fadd_rn(gy2,  a22);

    float s = __fadd_rn(__fadd_rn(__fmul_rn(gx2, gx2), __fmul_rn(gy2, gy2)), 1e-8f);
    float g = sqrtf(s);
    int gi = b * HW + y * W + xx;
    out_grad[gi] = g;
    // g^4 via two multiplies (replaces libdevice powf -- the hidden ~1.3 ms)
    float gg  = __fmul_rn(g, g);
    float g4  = __fmul_rn(gg, gg);
    float wgm = __fmul_rn(g4, 10.0f);

    float c0 = sc0[ly][lx], c1 = sc1[ly][lx], c2 = sc2[ly][lx];
    // dirs: 0:(−1,0) nb y+1 | 1:(1,0) nb y−1 | 2:(0,−1) nb x+1 | 3:(0,1) nb x−1
    const int ndy[4] = {1, -1, 0, 0};
    const int ndx[4] = {0, 0, 1, -1};
#pragma unroll
    for (int d = 0; d < 4; d++) {
        int ny = ly + ndy[d], nx = lx + ndx[d];
        float sc = __fadd_rn(__fadd_rn(fabsf(c0 - sc0[ny][nx]), fabsf(c1 - sc1[ny][nx])),
                             fabsf(c2 - sc2[ny][nx]));
        g_wcd[d][gi] = __fadd_rn(wgm, __fmul_rn(sc, 10.0f));
    }
    g_dist[0][gi] = INFINITY;
    g_mask[0][gi] = 255;
}

// ---------------- phase 2: nearest-minima snap + seed scatter ----------------
#define OCCW ((HW + 31) / 32)

__device__ __forceinline__ float wredminf(float v) {
#pragma unroll
    for (int o = 16; o; o >>= 1) v = fminf(v, __shfl_xor_sync(0xffffffffu, v, o));
    return v;
}
__device__ __forceinline__ int wredmini(int v) {
#pragma unroll
    for (int o = 16; o; o >>= 1) v = min(v, __shfl_xor_sync(0xffffffffu, v, o));
    return v;
}

__global__ void k_cents(const float* __restrict__ grad, float* __restrict__ cents_out) {
    extern __shared__ unsigned char smraw[];
    float*        sg  = (float*)smraw;
    unsigned int* occ = (unsigned int*)(smraw + (size_t)HW * sizeof(float));
    __shared__ float smv[NC];
    __shared__ int   sli[NC];

    int b = blockIdx.x;
    int tid = threadIdx.x;
    const float* gb = grad + b * HW;
    for (int i = tid; i < HW; i += TPB) sg[i] = gb[i];
    for (int i = tid; i < OCCW; i += TPB) occ[i] = 0u;
    __syncthreads();

    int warp = tid >> 5, lane = tid & 31;
    for (int k = warp; k < NC; k += 8) {
        int cy = 8 + 16 * (k / 14);
        int cx = 8 + 16 * (k % 14);
        int ymin = max(0, cy - NBR), ymax = min(H, cy + NBR);
        int xmin = max(0, cx - NBR), xmax = min(W, cx + NBR);
        int h = ymax - ymin, w = xmax - xmin;

        float colmin = INFINITY;
        bool lv = (lane < w) && (lane < WINS);
        if (lv) {
            const float* col = sg + ymin * W + xmin + lane;
#pragma unroll
            for (int wy = 0; wy < WINS; wy++) {
                if (wy < h) colmin = fminf(colmin, col[wy * W]);
            }
        }
        float mv = wredminf(colmin);
        int li = WINS * WINS;
        if (lv) {
            const float* col = sg + ymin * W + xmin + lane;
#pragma unroll
            for (int wy = 0; wy < WINS; wy++) {
                if (wy < h && col[wy * W] == mv) { li = wy * WINS + lane; break; }
            }
        }
        li = wredmini(li);
        if (lane == 0) { smv[k] = mv; sli[k] = li; }
    }
    __syncthreads();

    if (tid == 0) {
        for (int k = 0; k < NC; k++) {
            int cy = 8 + 16 * (k / 14);
            int cx = 8 + 16 * (k % 14);
            int ymin = max(0, cy - NBR), ymax = min(H, cy + NBR);
            int xmin = max(0, cx - NBR), xmax = min(W, cx + NBR);
            int h = ymax - ymin, w = xmax - xmin;
            int ny = cy, nx = cx;
            bool found = false;
            int li = sli[k];
            float mv = smv[k];
            if (li < WINS * WINS) {
                int py = ymin + li / WINS, px = xmin + li % WINS;
                int bi = py * W + px;
                if (!((occ[bi >> 5] >> (bi & 31)) & 1u)) {
                    ny = py; nx = px; found = true;
                } else {
                    for (int l2 = 0; l2 < WINS * WINS; l2++) {
                        int wy = l2 / WINS, wx = l2 % WINS;
                        if (wy < h && wx < w) {
                            int b2 = (ymin + wy) * W + (xmin + wx);
                            if (sg[b2] == mv && !((occ[b2 >> 5] >> (b2 & 31)) & 1u)) {
                                ny = ymin + wy; nx = xmin + wx; found = true; break;
                            }
                        }
                    }
                }
            }
            if (found) {
                int bi = ny * W + nx;
                occ[bi >> 5] |= (1u << (bi & 31));
            }
            cents_out[(b * NC + k) * 2 + 0] = (float)ny;
            cents_out[(b * NC + k) * 2 + 1] = (float)nx;
            int gi = b * HW + ny * W + nx;
            g_dist[0][gi] = 0.0f;
            g_mask[0][gi] = (unsigned char)k;
        }
    }
}

// ---------------- phase 3: 2-col/thread multi-warp propagation ---------------
#define SM_WC   0                       // float2 [4][RR][32] = 49152
#define SM_XAD  49152                   // float2 [8][32]     = 2048
#define SM_XBD  (49152 + 2048)          // float2 [8][32]     = 2048
#define SM_XAM  (49152 + 4096)          // uchar2 [8][32]     = 512
#define SM_XBM  (49152 + 4608)          // uchar2 [8][32]     = 512
#define PROP_SMEM (49152 + 5120)

__global__ __launch_bounds__(256, 4) void k_prop(int s, int niter, int last,
                                                 float* __restrict__ out_mask) {
    extern __shared__ unsigned char psm[];
    float2 (*sWc)[RR][32] = (float2(*)[RR][32])(psm + SM_WC);
    float2* xAD = (float2*)(psm + SM_XAD);
    float2* xBD = (float2*)(psm + SM_XBD);
    uchar2* xAM = (uchar2*)(psm + SM_XAM);
    uchar2* xBM = (uchar2*)(psm + SM_XBM);

    const int tid  = threadIdx.x;
    const int lane = tid & 31;
    const int w    = tid >> 5;
    const int ox = blockIdx.x * CC;
    const int oy = blockIdx.y * CR;
    const int b  = blockIdx.z;

    const float*         dIn = g_dist[s];
    const unsigned char* mIn = g_mask[s];

    // ---- load wcd into smem as float2 (coalesced) ---------------------------
    for (int idx = tid; idx < 4 * RR * 32; idx += 256) {
        int d  = idx / (RR * 32);
        int rm = idx - d * (RR * 32);
        int R  = rm >> 5;
        int L  = rm & 31;
        int gy = oy - HALO + R; gy += (gy < 0) ? H : 0; gy -= (gy >= H) ? H : 0;
        int gx = ox - HALO + 2 * L; gx += (gx < 0) ? W : 0; gx -= (gx >= W) ? W : 0;
        int gi = b * HW + gy * W + gx;
        sWc[d][R][L] = *(const float2*)(&g_wcd[d][gi]);
    }

    // ---- load own dist/mask columns -----------------------------------------
    int gx0 = ox - HALO + 2 * lane; gx0 += (gx0 < 0) ? W : 0; gx0 -= (gx0 >= W) ? W : 0;
    float d0[RPW], d1[RPW];
    int   m0[RPW], m1[RPW];
    int   gidx[RPW];
#pragma unroll
    for (int r = 0; r < RPW; r++) {
        int R = w * RPW + r;
        int gy = oy - HALO + R; gy += (gy < 0) ? H : 0; gy -= (gy >= H) ? H : 0;
        int gi = b * HW + gy * W + gx0;
        gidx[r] = gi;
        float2 dv = *(const float2*)(dIn + gi);
        uchar2 mv = *(const uchar2*)(mIn + gi);
        d0[r] = dv.x; d1[r] = dv.y;
        m0[r] = mv.x; m1[r] = mv.y;
    }
    __syncthreads();

#pragma unroll 1
    for (int it = 0; it < niter; it++) {
        // ---- pass 0: dir (-1,0), read y+1, rows ascending --------------------
        xAD[w * 32 + lane] = make_float2(d0[0], d1[0]);
        xAM[w * 32 + lane] = make_uchar2((unsigned char)m0[0], (unsigned char)m1[0]);
        __syncthreads();
#pragma unroll
        for (int r = 0; r < RPW - 1; r++) {
            float2 wc = sWc[0][w * RPW + r][lane];
            float f0 = __fadd_rn(d0[r + 1], wc.x); if (f0 < d0[r]) { d0[r] = f0; m0[r] = m0[r + 1]; }
            float f1 = __fadd_rn(d1[r + 1], wc.y); if (f1 < d1[r]) { d1[r] = f1; m1[r] = m1[r + 1]; }
        }
        {
            float2 nd = (w < PWARPS - 1) ? xAD[(w + 1) * 32 + lane] : make_float2(INFINITY, INFINITY);
            uchar2 nm = (w < PWARPS - 1) ? xAM[(w + 1) * 32 + lane] : make_uchar2(0, 0);
            float2 wc = sWc[0][w * RPW + RPW - 1][lane];
            float f0 = __fadd_rn(nd.x, wc.x); if (f0 < d0[RPW - 1]) { d0[RPW - 1] = f0; m0[RPW - 1] = nm.x; }
            float f1 = __fadd_rn(nd.y, wc.y); if (f1 < d1[RPW - 1]) { d1[RPW - 1] = f1; m1[RPW - 1] = nm.y; }
        }
        // ---- pass 1: dir (1,0), read y-1, rows descending ---------------------
        xBD[w * 32 + lane] = make_float2(d0[RPW - 1], d1[RPW - 1]);
        xBM[w * 32 + lane] = make_uchar2((unsigned char)m0[RPW - 1], (unsigned char)m1[RPW - 1]);
        __syncthreads();
#pragma unroll
        for (int r = RPW - 1; r > 0; r--) {
            float2 wc = sWc[1][w * RPW + r][lane];
            float f0 = __fadd_rn(d0[r - 1], wc.x); if (f0 < d0[r]) { d0[r] = f0; m0[r] = m0[r - 1]; }
            float f1 = __fadd_rn(d1[r - 1], wc.y); if (f1 < d1[r]) { d1[r] = f1; m1[r] = m1[r - 1]; }
        }
        {
            float2 nd = (w > 0) ? xBD[(w - 1) * 32 + lane] : make_float2(INFINITY, INFINITY);
            uchar2 nm = (w > 0) ? xBM[(w - 1) * 32 + lane] : make_uchar2(0, 0);
            float2 wc = sWc[1][w * RPW][lane];
            float f0 = __fadd_rn(nd.x, wc.x); if (f0 < d0[0]) { d0[0] = f0; m0[0] = nm.x; }
            float f1 = __fadd_rn(nd.y, wc.y); if (f1 < d1[0]) { d1[0] = f1; m1[0] = nm.y; }
        }
        // ---- pass 2: dir (0,-1), read x+1 -------------------------------------
#pragma unroll
        for (int r = 0; r < RPW; r++) {
            float o0 = d0[r], o1 = d1[r];
            int   q0 = m0[r], q1 = m1[r];
            float sh = __shfl_down_sync(0xffffffffu, o0, 1);
            int   sm = __shfl_down_sync(0xffffffffu, q0, 1);
            float2 wc = sWc[2][w * RPW + r][lane];
            float f0 = __fadd_rn(o1, wc.x); if (f0 < o0) { d0[r] = f0; m0[r] = q1; }
            float f1 = __fadd_rn(sh, wc.y); if (f1 < o1) { d1[r] = f1; m1[r] = sm; }
        }
        // ---- pass 3: dir (0,1), read x-1 --------------------------------------
#pragma unroll
        for (int r = 0; r < RPW; r++) {
            float o0 = d0[r], o1 = d1[r];
            int   q0 = m0[r], q1 = m1[r];
            float sh = __shfl_up_sync(0xffffffffu, o1, 1);
            int   sm = __shfl_up_sync(0xffffffffu, q1, 1);
            float2 wc = sWc[3][w * RPW + r][lane];
            float f1 = __fadd_rn(o0, wc.y); if (f1 < o1) { d1[r] = f1; m1[r] = q0; }
            float f0 = __fadd_rn(sh, wc.x); if (f0 < o0) { d0[r] = f0; m0[r] = sm; }
        }
    }

    // ---- store central CC x CR ------------------------------------------------
    if (lane >= 4 && lane < 28) {
        int gx = ox - HALO + 2 * lane;              // un-wrapped; central => >= 0
        if (gx < W) {                               // guard right-edge padding tile
            if (!last) {
                float*         dOut = g_dist[s ^ 1];
                unsigned char* mOut = g_mask[s ^ 1];
#pragma unroll
                for (int r = 0; r < RPW; r++) {
                    int R = w * RPW + r;
                    if (R >= HALO && R < HALO + CR) {
                        int gi = gidx[r];
                        *(float2*)(dOut + gi) = make_float2(d0[r], d1[r]);
                        *(uchar2*)(mOut + gi) = make_uchar2((unsigned char)m0[r], (unsigned char)m1[r]);
                    }
                }
            } else {
#pragma unroll
                for (int r = 0; r < RPW; r++) {
                    int R = w * RPW + r;
                    if (R >= HALO && R < HALO + CR) {
                        int gi = gidx[r];
                        float v0 = (m0[r] == 255) ? -1.0f : (float)m0[r];
                        float v1 = (m1[r] == 255) ? -1.0f : (float)m1[r];
                        *(float2*)(out_mask + gi) = make_float2(v0, v1);
                    }
                }
            }
        }
    }
}

// ---------------- launch ------------------------------------------------------
extern "C" void kernel_launch(void* const* d_in, const int* in_sizes, int n_in,
                              void* d_out, int out_size) {
    const float* x = (const float*)d_in[0];
    float* out = (float*)d_out;
    float* out_grad  = out;                       // (B,1,H,W)
    float* out_cents = out + NTOT;                // (B,196,2)
    float* out_mask  = out + NTOT + B * NC * 2;   // (B,H,W)

    static const size_t centsSmem = (size_t)HW * sizeof(float) + (size_t)OCCW * sizeof(unsigned int);
    cudaFuncSetAttribute(k_cents, cudaFuncAttributeMaxDynamicSharedMemorySize, (int)centsSmem);
    cudaFuncSetAttribute(k_prop, cudaFuncAttributeMaxDynamicSharedMemorySize, PROP_SMEM);

    dim3 gg(W / 32, H / 8, B);                    // 7 x 28 x 64
    k_gradwcd<<<gg, 256>>>(x, out_grad);
    k_cents  <<<B, TPB, centsSmem>>>(out_grad, out_cents);

    dim3 pg((W + CC - 1) / CC, H / CR, B);        // 5 x 7 x 64
    int s = 0;
    int remaining = ITERS;
    while (remaining > 0) {
        int it = remaining >= HALO ? HALO : remaining;
        remaining -= it;
        int last = (remaining == 0) ? 1 : 0;
        k_prop<<<pg, 256, PROP_SMEM>>>(s, it, last, out_mask);
        s ^= 1;
    }
}

// round 8
// speedup vs baseline: 4.0330x; 3.3709x over previous
#include <cuda_runtime.h>
#include <math.h>
#include <float.h>

#define B    64
#define H    224
#define W    224
#define HW   (H*W)
#define NTOT (B*HW)
#define NC   196
#define NBR  10
#define WINS 20
#define ITERS 50

// propagation tile geometry
#define HALO  8
#define CC    48            // central cols
#define CR    32            // central rows
#define RC    64            // region cols  = CC + 2*HALO
#define RR    48            // region rows  = CR + 2*HALO
#define PWARPS 8
#define RPW   6             // rows per warp
#define TPB   256

// ---------------- scratch (static device globals) ---------------------------
__device__ float         g_wcd [4][NTOT];     // wgm + 10*cdiff[d]
__device__ float         g_dist[2][NTOT];
__device__ unsigned char g_mask[2][NTOT];

// ---------------- spacer no-op (aligns ncu -s 5 onto k_cents) ----------------
__global__ void k_nop() {}

// ---------------- phase 1: fused gray/sobel/wgm/wcd + init (smem-tiled) ------
#define GT_W 34
#define GT_H 10

__global__ __launch_bounds__(256) void k_gradwcd(const float* __restrict__ x,
                                                 float* __restrict__ out_grad) {
    __shared__ float sc0[GT_H][GT_W];
    __shared__ float sc1[GT_H][GT_W];
    __shared__ float sc2[GT_H][GT_W];
    __shared__ float sgr[GT_H][GT_W];

    const int tid = threadIdx.x;
    const int ox = blockIdx.x * 32;
    const int oy = blockIdx.y * 8;
    const int b  = blockIdx.z;
    const float* xb = x + (size_t)b * 3 * HW;

    for (int idx = tid; idx < GT_W * GT_H; idx += 256) {
        int ly = idx / GT_W, lx = idx - ly * GT_W;
        int gy = oy - 1 + ly; gy += (gy < 0) ? H : 0; gy -= (gy >= H) ? H : 0;
        int gx = ox - 1 + lx; gx += (gx < 0) ? W : 0; gx -= (gx >= W) ? W : 0;
        int gi = gy * W + gx;
        float R = xb[gi], G = xb[HW + gi], Bv = xb[2 * HW + gi];
        sc0[ly][lx] = R; sc1[ly][lx] = G; sc2[ly][lx] = Bv;
        float t = __fadd_rn(__fmul_rn(0.2989f, R), __fmul_rn(0.587f, G));
        sgr[ly][lx] = __fadd_rn(t, __fmul_rn(0.114f, Bv));
    }
    __syncthreads();

    const int tx = tid & 31, ty = tid >> 5;
    const int y = oy + ty, xx = ox + tx;
    const int ly = ty + 1, lx = tx + 1;

    #define TAP(dy, dx) ((((unsigned)(y + (dy)) < (unsigned)H) && ((unsigned)(xx + (dx)) < (unsigned)W)) ? sgr[ly + (dy)][lx + (dx)] : 0.0f)
    float a00 = TAP(-1,-1), a01 = TAP(-1,0), a02 = TAP(-1,1);
    float a10 = TAP(0,-1),                   a12 = TAP(0,1);
    float a20 = TAP(1,-1),  a21 = TAP(1,0),  a22 = TAP(1,1);
    #undef TAP

    float gx2 = __fadd_rn(-a00, a02);
    gx2 = __fadd_rn(gx2, __fmul_rn(-2.0f, a10));
    gx2 = __fadd_rn(gx2, __fmul_rn( 2.0f, a12));
    gx2 = __fadd_rn(gx2, -a20);
    gx2 = __fadd_rn(gx2,  a22);
    float gy2 = __fadd_rn(-a00, __fmul_rn(-2.0f, a01));
    gy2 = __fadd_rn(gy2, -a02);
    gy2 = __fadd_rn(gy2,  a20);
    gy2 = __fadd_rn(gy2, __fmul_rn(2.0f, a21));
    gy2 = __fadd_rn(gy2,  a22);

    float s = __fadd_rn(__fadd_rn(__fmul_rn(gx2, gx2), __fmul_rn(gy2, gy2)), 1e-8f);
    float g = sqrtf(s);
    int gi = b * HW + y * W + xx;
    out_grad[gi] = g;
    float gg  = __fmul_rn(g, g);
    float g4  = __fmul_rn(gg, gg);
    float wgm = __fmul_rn(g4, 10.0f);

    float c0 = sc0[ly][lx], c1 = sc1[ly][lx], c2 = sc2[ly][lx];
    const int ndy[4] = {1, -1, 0, 0};
    const int ndx[4] = {0, 0, 1, -1};
#pragma unroll
    for (int d = 0; d < 4; d++) {
        int ny = ly + ndy[d], nx = lx + ndx[d];
        float sc = __fadd_rn(__fadd_rn(fabsf(c0 - sc0[ny][nx]), fabsf(c1 - sc1[ny][nx])),
                             fabsf(c2 - sc2[ny][nx]));
        g_wcd[d][gi] = __fadd_rn(wgm, __fmul_rn(sc, 10.0f));
    }
    g_dist[0][gi] = INFINITY;
    g_mask[0][gi] = 255;
}

// ---------------- phase 2: nearest-minima snap + seed scatter ----------------
#define OCCW ((HW + 31) / 32)

__device__ __forceinline__ float wredminf(float v) {
#pragma unroll
    for (int o = 16; o; o >>= 1) v = fminf(v, __shfl_xor_sync(0xffffffffu, v, o));
    return v;
}
__device__ __forceinline__ int wredmini(int v) {
#pragma unroll
    for (int o = 16; o; o >>= 1) v = min(v, __shfl_xor_sync(0xffffffffu, v, o));
    return v;
}

__global__ void k_cents(const float* __restrict__ grad, float* __restrict__ cents_out) {
    extern __shared__ unsigned char smraw[];
    float*        sg  = (float*)smraw;
    unsigned int* occ = (unsigned int*)(smraw + (size_t)HW * sizeof(float));
    __shared__ float smv[NC];
    __shared__ int   sli[NC];

    int b = blockIdx.x;
    int tid = threadIdx.x;
    const float* gb = grad + b * HW;
    for (int i = tid; i < HW; i += TPB) sg[i] = gb[i];
    for (int i = tid; i < OCCW; i += TPB) occ[i] = 0u;
    __syncthreads();

    int warp = tid >> 5, lane = tid & 31;
    // ---- phase A: per-window min + raster-first min index (occ-blind) -------
    for (int k = warp; k < NC; k += 8) {
        int cy = 8 + 16 * (k / 14);
        int cx = 8 + 16 * (k % 14);
        int ymin = max(0, cy - NBR), ymax = min(H, cy + NBR);
        int xmin = max(0, cx - NBR), xmax = min(W, cx + NBR);
        int h = ymax - ymin, w = xmax - xmin;

        float colmin = INFINITY;
        bool lv = (lane < w) && (lane < WINS);
        if (lv) {
            const float* col = sg + ymin * W + xmin + lane;
#pragma unroll
            for (int wy = 0; wy < WINS; wy++) {
                if (wy < h) colmin = fminf(colmin, col[wy * W]);
            }
        }
        float mv = wredminf(colmin);
        int li = WINS * WINS;
        if (lv) {
            const float* col = sg + ymin * W + xmin + lane;
#pragma unroll
            for (int wy = 0; wy < WINS; wy++) {
                if (wy < h && col[wy * W] == mv) { li = wy * WINS + lane; break; }
            }
        }
        li = wredmini(li);
        if (lane == 0) { smv[k] = mv; sli[k] = li; }
    }
    __syncthreads();

    // ---- phase B: warp-cooperative sequential resolve (warp 0) ---------------
    if (warp == 0) {
        const int wy0 = lane / WINS;            // lane-constant rescan start
        const int wx0 = lane - wy0 * WINS;
        for (int k = 0; k < NC; k++) {
            int cy = 8 + 16 * (k / 14);
            int cx = 8 + 16 * (k % 14);
            int ymin = max(0, cy - NBR), ymax = min(H, cy + NBR);
            int xmin = max(0, cx - NBR), xmax = min(W, cx + NBR);
            int h = ymax - ymin, w = xmax - xmin;
            int ny = cy, nx = cx;
            bool found = false;
            int li = sli[k];
            float mv = smv[k];
            if (li < WINS * WINS) {
                int py = ymin + li / WINS, px = xmin + li % WINS;
                int bi = py * W + px;
                bool occupied = (occ[bi >> 5] >> (bi & 31)) & 1u;   // lane-uniform
                if (!occupied) {
                    ny = py; nx = px; found = true;
                } else {
                    // warp-parallel rescan for raster-first unoccupied min
                    int best = WINS * WINS;
                    int wy = wy0, wx = wx0;
#pragma unroll
                    for (int t = 0; t < 13; t++) {
                        int idx = lane + 32 * t;
                        if (idx < WINS * WINS && wy < h && wx < w) {
                            int b2 = (ymin + wy) * W + (xmin + wx);
                            if (sg[b2] == mv && !((occ[b2 >> 5] >> (b2 & 31)) & 1u))
                                best = min(best, idx);
                        }
                        wx += 12; wy += 1;
                        if (wx >= WINS) { wx -= WINS; wy += 1; }
                    }
                    best = wredmini(best);
                    if (best < WINS * WINS) {
                        ny = ymin + best / WINS;
                        nx = xmin + best % WINS;
                        found = true;
                    }
                }
            }
            if (lane == 0) {
                if (found) {
                    int bi = ny * W + nx;
                    occ[bi >> 5] |= (1u << (bi & 31));
                }
                cents_out[(b * NC + k) * 2 + 0] = (float)ny;
                cents_out[(b * NC + k) * 2 + 1] = (float)nx;
                int gi = b * HW + ny * W + nx;
                g_dist[0][gi] = 0.0f;
                g_mask[0][gi] = (unsigned char)k;
            }
            __syncwarp();
        }
    }
}

// ---------------- phase 3: 2-col/thread multi-warp propagation ---------------
#define SM_WC   0                       // float2 [4][RR][32] = 49152
#define SM_XAD  49152                   // float2 [8][32]     = 2048
#define SM_XBD  (49152 + 2048)          // float2 [8][32]     = 2048
#define SM_XAM  (49152 + 4096)          // uchar2 [8][32]     = 512
#define SM_XBM  (49152 + 4608)          // uchar2 [8][32]     = 512
#define PROP_SMEM (49152 + 5120)

__global__ __launch_bounds__(256, 4) void k_prop(int s, int niter, int last,
                                                 float* __restrict__ out_mask) {
    extern __shared__ unsigned char psm[];
    float2 (*sWc)[RR][32] = (float2(*)[RR][32])(psm + SM_WC);
    float2* xAD = (float2*)(psm + SM_XAD);
    float2* xBD = (float2*)(psm + SM_XBD);
    uchar2* xAM = (uchar2*)(psm + SM_XAM);
    uchar2* xBM = (uchar2*)(psm + SM_XBM);

    const int tid  = threadIdx.x;
    const int lane = tid & 31;
    const int w    = tid >> 5;
    const int ox = blockIdx.x * CC;
    const int oy = blockIdx.y * CR;
    const int b  = blockIdx.z;

    const float*         dIn = g_dist[s];
    const unsigned char* mIn = g_mask[s];

    for (int idx = tid; idx < 4 * RR * 32; idx += 256) {
        int d  = idx / (RR * 32);
        int rm = idx - d * (RR * 32);
        int R  = rm >> 5;
        int L  = rm & 31;
        int gy = oy - HALO + R; gy += (gy < 0) ? H : 0; gy -= (gy >= H) ? H : 0;
        int gx = ox - HALO + 2 * L; gx += (gx < 0) ? W : 0; gx -= (gx >= W) ? W : 0;
        int gi = b * HW + gy * W + gx;
        sWc[d][R][L] = *(const float2*)(&g_wcd[d][gi]);
    }

    int gx0 = ox - HALO + 2 * lane; gx0 += (gx0 < 0) ? W : 0; gx0 -= (gx0 >= W) ? W : 0;
    float d0[RPW], d1[RPW];
    int   m0[RPW], m1[RPW];
    int   gidx[RPW];
#pragma unroll
    for (int r = 0; r < RPW; r++) {
        int R = w * RPW + r;
        int gy = oy - HALO + R; gy += (gy < 0) ? H : 0; gy -= (gy >= H) ? H : 0;
        int gi = b * HW + gy * W + gx0;
        gidx[r] = gi;
        float2 dv = *(const float2*)(dIn + gi);
        uchar2 mv = *(const uchar2*)(mIn + gi);
        d0[r] = dv.x; d1[r] = dv.y;
        m0[r] = mv.x; m1[r] = mv.y;
    }
    __syncthreads();

#pragma unroll 1
    for (int it = 0; it < niter; it++) {
        // ---- pass 0: dir (-1,0), read y+1, rows ascending --------------------
        xAD[w * 32 + lane] = make_float2(d0[0], d1[0]);
        xAM[w * 32 + lane] = make_uchar2((unsigned char)m0[0], (unsigned char)m1[0]);
        __syncthreads();
#pragma unroll
        for (int r = 0; r < RPW - 1; r++) {
            float2 wc = sWc[0][w * RPW + r][lane];
            float f0 = __fadd_rn(d0[r + 1], wc.x); if (f0 < d0[r]) { d0[r] = f0; m0[r] = m0[r + 1]; }
            float f1 = __fadd_rn(d1[r + 1], wc.y); if (f1 < d1[r]) { d1[r] = f1; m1[r] = m1[r + 1]; }
        }
        {
            float2 nd = (w < PWARPS - 1) ? xAD[(w + 1) * 32 + lane] : make_float2(INFINITY, INFINITY);
            uchar2 nm = (w < PWARPS - 1) ? xAM[(w + 1) * 32 + lane] : make_uchar2(0, 0);
            float2 wc = sWc[0][w * RPW + RPW - 1][lane];
            float f0 = __fadd_rn(nd.x, wc.x); if (f0 < d0[RPW - 1]) { d0[RPW - 1] = f0; m0[RPW - 1] = nm.x; }
            float f1 = __fadd_rn(nd.y, wc.y); if (f1 < d1[RPW - 1]) { d1[RPW - 1] = f1; m1[RPW - 1] = nm.y; }
        }
        // ---- pass 1: dir (1,0), read y-1, rows descending ---------------------
        xBD[w * 32 + lane] = make_float2(d0[RPW - 1], d1[RPW - 1]);
        xBM[w * 32 + lane] = make_uchar2((unsigned char)m0[RPW - 1], (unsigned char)m1[RPW - 1]);
        __syncthreads();
#pragma unroll
        for (int r = RPW - 1; r > 0; r--) {
            float2 wc = sWc[1][w * RPW + r][lane];
            float f0 = __fadd_rn(d0[r - 1], wc.x); if (f0 < d0[r]) { d0[r] = f0; m0[r] = m0[r - 1]; }
            float f1 = __fadd_rn(d1[r - 1], wc.y); if (f1 < d1[r]) { d1[r] = f1; m1[r] = m1[r - 1]; }
        }
        {
            float2 nd = (w > 0) ? xBD[(w - 1) * 32 + lane] : make_float2(INFINITY, INFINITY);
            uchar2 nm = (w > 0) ? xBM[(w - 1) * 32 + lane] : make_uchar2(0, 0);
            float2 wc = sWc[1][w * RPW][lane];
            float f0 = __fadd_rn(nd.x, wc.x); if (f0 < d0[0]) { d0[0] = f0; m0[0] = nm.x; }
            float f1 = __fadd_rn(nd.y, wc.y); if (f1 < d1[0]) { d1[0] = f1; m1[0] = nm.y; }
        }
        // ---- pass 2: dir (0,-1), read x+1 -------------------------------------
#pragma unroll
        for (int r = 0; r < RPW; r++) {
            float o0 = d0[r], o1 = d1[r];
            int   q0 = m0[r], q1 = m1[r];
            float sh = __shfl_down_sync(0xffffffffu, o0, 1);
            int   sm = __shfl_down_sync(0xffffffffu, q0, 1);
            float2 wc = sWc[2][w * RPW + r][lane];
            float f0 = __fadd_rn(o1, wc.x); if (f0 < o0) { d0[r] = f0; m0[r] = q1; }
            float f1 = __fadd_rn(sh, wc.y); if (f1 < o1) { d1[r] = f1; m1[r] = sm; }
        }
        // ---- pass 3: dir (0,1), read x-1 --------------------------------------
#pragma unroll
        for (int r = 0; r < RPW; r++) {
            float o0 = d0[r], o1 = d1[r];
            int   q0 = m0[r], q1 = m1[r];
            float sh = __shfl_up_sync(0xffffffffu, o1, 1);
            int   sm = __shfl_up_sync(0xffffffffu, q1, 1);
            float2 wc = sWc[3][w * RPW + r][lane];
            float f1 = __fadd_rn(o0, wc.y); if (f1 < o1) { d1[r] = f1; m1[r] = q0; }
            float f0 = __fadd_rn(sh, wc.x); if (f0 < o0) { d0[r] = f0; m0[r] = sm; }
        }
    }

    // ---- store central CC x CR ------------------------------------------------
    if (lane >= 4 && lane < 28) {
        int gx = ox - HALO + 2 * lane;
        if (gx < W) {
            if (!last) {
                float*         dOut = g_dist[s ^ 1];
                unsigned char* mOut = g_mask[s ^ 1];
#pragma unroll
                for (int r = 0; r < RPW; r++) {
                    int R = w * RPW + r;
                    if (R >= HALO && R < HALO + CR) {
                        int gi = gidx[r];
                        *(float2*)(dOut + gi) = make_float2(d0[r], d1[r]);
                        *(uchar2*)(mOut + gi) = make_uchar2((unsigned char)m0[r], (unsigned char)m1[r]);
                    }
                }
            } else {
#pragma unroll
                for (int r = 0; r < RPW; r++) {
                    int R = w * RPW + r;
                    if (R >= HALO && R < HALO + CR) {
                        int gi = gidx[r];
                        float v0 = (m0[r] == 255) ? -1.0f : (float)m0[r];
                        float v1 = (m1[r] == 255) ? -1.0f : (float)m1[r];
                        *(float2*)(out_mask + gi) = make_float2(v0, v1);
                    }
                }
            }
        }
    }
}

// ---------------- launch ------------------------------------------------------
extern "C" void kernel_launch(void* const* d_in, const int* in_sizes, int n_in,
                              void* d_out, int out_size) {
    const float* x = (const float*)d_in[0];
    float* out = (float*)d_out;
    float* out_grad  = out;                       // (B,1,H,W)
    float* out_cents = out + NTOT;                // (B,196,2)
    float* out_mask  = out + NTOT + B * NC * 2;   // (B,H,W)

    static const size_t centsSmem = (size_t)HW * sizeof(float) + (size_t)OCCW * sizeof(unsigned int);
    cudaFuncSetAttribute(k_cents, cudaFuncAttributeMaxDynamicSharedMemorySize, (int)centsSmem);
    cudaFuncSetAttribute(k_prop, cudaFuncAttributeMaxDynamicSharedMemorySize, PROP_SMEM);

    dim3 gg(W / 32, H / 8, B);                    // 7 x 28 x 64
    k_gradwcd<<<gg, 256>>>(x, out_grad);
    // spacers so ncu (-s 5 -c 1) profiles k_cents as launch #6
    k_nop<<<1, 1>>>();
    k_nop<<<1, 1>>>();
    k_nop<<<1, 1>>>();
    k_nop<<<1, 1>>>();
    k_cents<<<B, TPB, centsSmem>>>(out_grad, out_cents);

    dim3 pg((W + CC - 1) / CC, H / CR, B);        // 5 x 7 x 64
    int s = 0;
    int remaining = ITERS;
    while (remaining > 0) {
        int it = remaining >= HALO ? HALO : remaining;
        remaining -= it;
        int last = (remaining == 0) ? 1 : 0;
        k_prop<<<pg, 256, PROP_SMEM>>>(s, it, last, out_mask);
        s ^= 1;
    }
}